// round 2
// baseline (speedup 1.0000x reference)
#include <cuda_runtime.h>

#define NN 50000
#define NE 800000
#define NG 512

// ---------------- device scratch (static, no runtime alloc) ----------------
__device__ float g_h0[NN * 128];
__device__ float g_h1[NN * 128];
__device__ float g_P [NN * 512];     // node projections [fd|sd|fs|ss]; reused as MLP temporaries
__device__ float g_Wcat[512 * 128];
__device__ float g_bcat[512];
__device__ float g_pool[NG * 128];
__device__ float g_t0g[NG * 256];
__device__ float g_t1g[NG * 256];
__device__ float g_gfin[NG * 128];

// ---------------- f32x2 helpers ----------------
typedef unsigned long long u64;
__device__ __forceinline__ u64 pk2(float lo, float hi) {
    u64 r; asm("mov.b64 %0,{%1,%2};" : "=l"(r) : "f"(lo), "f"(hi)); return r;
}
__device__ __forceinline__ float2 up2(u64 v) {
    float2 r; asm("mov.b64 {%0,%1},%2;" : "=f"(r.x), "=f"(r.y) : "l"(v)); return r;
}
__device__ __forceinline__ u64 ffma2(u64 a, u64 b, u64 c) {
    u64 d; asm("fma.rn.f32x2 %0,%1,%2,%3;" : "=l"(d) : "l"(a), "l"(b), "l"(c)); return d;
}
__device__ __forceinline__ u64 fadd2(u64 a, u64 b) {
    u64 d; asm("add.rn.f32x2 %0,%1,%2;" : "=l"(d) : "l"(a), "l"(b)); return d;
}
union F4U { float4 f4; u64 u[2]; float f[4]; };

__device__ __forceinline__ void red4(float* addr, float4 v) {
    asm volatile("red.global.add.v4.f32 [%0], {%1,%2,%3,%4};"
                 :: "l"(addr), "f"(v.x), "f"(v.y), "f"(v.z), "f"(v.w) : "memory");
}

__device__ __forceinline__ float sigm(float x) { return 1.f / (1.f + __expf(-x)); }
__device__ __forceinline__ float softp(float x) { return fmaxf(x, 0.f) + log1pf(__expf(-fabsf(x))); }

// ---------------- pack concatenated projection weights ----------------
// Wcat[n][k], n in [0,512): n<128 Wf_dst row n; <256 Ws_dst; <384 Wf_src; <512 Ws_src
__global__ void pack_wcat(const float* __restrict__ Wf, const float* __restrict__ Ws,
                          const float* __restrict__ bf, const float* __restrict__ bs,
                          float* __restrict__ Wcat, float* __restrict__ bcat, int layer) {
    int idx = blockIdx.x * blockDim.x + threadIdx.x;
    if (idx < 512) {
        float b = 0.f;
        if (idx < 128) b = bf[layer * 128 + idx];
        else if (idx < 256) b = bs[layer * 128 + idx - 128];
        bcat[idx] = b;
    }
    if (idx >= 512 * 128) return;
    int n = idx >> 7, k = idx & 127;
    const float* W; int o, koff;
    if      (n < 128) { W = Wf; o = n;       koff = 0;   }
    else if (n < 256) { W = Ws; o = n - 128; koff = 0;   }
    else if (n < 384) { W = Wf; o = n - 256; koff = 128; }
    else              { W = Ws; o = n - 384; koff = 128; }
    Wcat[idx] = W[((size_t)(layer * 128 + o)) * 320 + koff + k];
}

// ---------------- generic SGEMM: C[M,N] = act(A[M,K] @ B[N,K]^T + bias (+res)) ----------------
// 128x128 tile, BK=8, 256 threads, 8x8 microtile, f32x2 FMA.
__global__ void __launch_bounds__(256) sgemm_bt(
    const float* __restrict__ A, const float* __restrict__ B,
    const float* __restrict__ bias, const float* __restrict__ res,
    float* __restrict__ C, int M, int N, int K, int relu) {
    __shared__ float As[8][128];
    __shared__ float Bs[8][128];
    int tid = threadIdx.x;
    int m0 = blockIdx.y * 128;
    int n0 = blockIdx.x * 128;
    int tx = tid & 15, ty = tid >> 4;
    int lr = tid >> 1;            // 0..127
    int lk = (tid & 1) * 4;       // 0 or 4

    u64 acc[8][4];
#pragma unroll
    for (int i = 0; i < 8; i++)
#pragma unroll
        for (int j = 0; j < 4; j++) acc[i][j] = 0ull;

    for (int k0 = 0; k0 < K; k0 += 8) {
        float4 av = make_float4(0.f, 0.f, 0.f, 0.f);
        int arow = m0 + lr;
        if (arow < M) av = *(const float4*)(A + (size_t)arow * K + k0 + lk);
        As[lk + 0][lr] = av.x; As[lk + 1][lr] = av.y;
        As[lk + 2][lr] = av.z; As[lk + 3][lr] = av.w;
        float4 bv = *(const float4*)(B + (size_t)(n0 + lr) * K + k0 + lk);
        Bs[lk + 0][lr] = bv.x; Bs[lk + 1][lr] = bv.y;
        Bs[lk + 2][lr] = bv.z; Bs[lk + 3][lr] = bv.w;
        __syncthreads();
#pragma unroll
        for (int k = 0; k < 8; k++) {
            F4U b0, b1;
            b0.f4 = *(const float4*)&Bs[k][tx * 8];
            b1.f4 = *(const float4*)&Bs[k][tx * 8 + 4];
            float4 a0 = *(const float4*)&As[k][ty * 8];
            float4 a1 = *(const float4*)&As[k][ty * 8 + 4];
            float a[8] = {a0.x, a0.y, a0.z, a0.w, a1.x, a1.y, a1.z, a1.w};
#pragma unroll
            for (int i = 0; i < 8; i++) {
                u64 ai = pk2(a[i], a[i]);
                acc[i][0] = ffma2(ai, b0.u[0], acc[i][0]);
                acc[i][1] = ffma2(ai, b0.u[1], acc[i][1]);
                acc[i][2] = ffma2(ai, b1.u[0], acc[i][2]);
                acc[i][3] = ffma2(ai, b1.u[1], acc[i][3]);
            }
        }
        __syncthreads();
    }

#pragma unroll
    for (int i = 0; i < 8; i++) {
        int row = m0 + ty * 8 + i;
        if (row >= M) continue;
        int n = n0 + tx * 8;
        float o[8];
#pragma unroll
        for (int j2 = 0; j2 < 4; j2++) {
            float2 v = up2(acc[i][j2]);
            o[2 * j2] = v.x; o[2 * j2 + 1] = v.y;
        }
#pragma unroll
        for (int j = 0; j < 8; j++) {
            float v = o[j] + bias[n + j];
            if (res) v += res[(size_t)row * N + n + j];
            if (relu) v = fmaxf(v, 0.f);
            o[j] = v;
        }
        *(float4*)(C + (size_t)row * N + n)     = make_float4(o[0], o[1], o[2], o[3]);
        *(float4*)(C + (size_t)row * N + n + 4) = make_float4(o[4], o[5], o[6], o[7]);
    }
}

// ---------------- fused edge kernel ----------------
// per edge: f = P[dst][0:128] + P[src][256:384] + Wf_e @ ea
//           s = P[dst][128:256] + P[src][384:512] + Ws_e @ ea
//           red4(hout[dst], sigmoid(f)*softplus(s))
// Weights (64KB) resident in shared; 4 edges per warp iteration amortize weight LDS;
// edge_attr pre-duplicated into f32x2 pairs in shared for broadcast reads.
__global__ void __launch_bounds__(256, 2) edge_kernel(
    const float* __restrict__ Pall, const int* __restrict__ ei,
    const float* __restrict__ ea, const float* __restrict__ Wf,
    const float* __restrict__ Ws, int layer, float* __restrict__ hout) {
    extern __shared__ float smem[];
    float* sWf = smem;                  // [64][128]  (k-major: sWf[k*128+o] = Wf_e[o][k])
    float* sWs = smem + 64 * 128;
    u64*   sEa = (u64*)(smem + 2 * 64 * 128);   // [8 warps][4 edges][64]

    int tid = threadIdx.x;
    {
        const float* wfb = Wf + (size_t)layer * 128 * 320 + 256;
        const float* wsb = Ws + (size_t)layer * 128 * 320 + 256;
        for (int idx = tid; idx < 64 * 128; idx += 256) {
            int k = idx >> 7, o = idx & 127;
            sWf[idx] = wfb[(size_t)o * 320 + k];
            sWs[idx] = wsb[(size_t)o * 320 + k];
        }
    }
    __syncthreads();

    int w = tid >> 5, lane = tid & 31;
    u64* myEa = sEa + (size_t)w * 4 * 64;
    const float4* wf4 = (const float4*)sWf;
    const float4* ws4 = (const float4*)sWs;

    int gw = blockIdx.x * 8 + w;
    int nw = gridDim.x * 8;
    const int ngr = NE / 4;

    for (int g = gw; g < ngr; g += nw) {
        int e0 = g * 4;
        int idxv = 0;
        if (lane < 8) idxv = ei[(lane < 4 ? 0 : NE) + e0 + (lane & 3)];
#pragma unroll
        for (int t = 0; t < 4; t++) {
            float v0 = ea[(size_t)(e0 + t) * 64 + lane];
            float v1 = ea[(size_t)(e0 + t) * 64 + 32 + lane];
            myEa[t * 64 + lane]      = pk2(v0, v0);
            myEa[t * 64 + 32 + lane] = pk2(v1, v1);
        }
        u64 aF[4][2], aS[4][2];
        int dsts[4];
#pragma unroll
        for (int t = 0; t < 4; t++) {
            int s = __shfl_sync(0xffffffffu, idxv, t);
            int d = __shfl_sync(0xffffffffu, idxv, 4 + t);
            dsts[t] = d;
            const float4* pd = (const float4*)(Pall + (size_t)d * 512);
            const float4* ps = (const float4*)(Pall + (size_t)s * 512);
            F4U fd, sd, fs, ss;
            fd.f4 = pd[lane];       // fd cols 4*lane..+3
            sd.f4 = pd[32 + lane];
            fs.f4 = ps[64 + lane];
            ss.f4 = ps[96 + lane];
            aF[t][0] = fadd2(fd.u[0], fs.u[0]); aF[t][1] = fadd2(fd.u[1], fs.u[1]);
            aS[t][0] = fadd2(sd.u[0], ss.u[0]); aS[t][1] = fadd2(sd.u[1], ss.u[1]);
        }
        __syncwarp();
#pragma unroll 4
        for (int k = 0; k < 64; k++) {
            F4U wf, ws;
            wf.f4 = wf4[k * 32 + lane];
            ws.f4 = ws4[k * 32 + lane];
#pragma unroll
            for (int t = 0; t < 4; t++) {
                u64 e2 = myEa[t * 64 + k];
                aF[t][0] = ffma2(wf.u[0], e2, aF[t][0]);
                aF[t][1] = ffma2(wf.u[1], e2, aF[t][1]);
                aS[t][0] = ffma2(ws.u[0], e2, aS[t][0]);
                aS[t][1] = ffma2(ws.u[1], e2, aS[t][1]);
            }
        }
#pragma unroll
        for (int t = 0; t < 4; t++) {
            float2 f0 = up2(aF[t][0]), f1 = up2(aF[t][1]);
            float2 s0 = up2(aS[t][0]), s1 = up2(aS[t][1]);
            float4 m;
            m.x = sigm(f0.x) * softp(s0.x);
            m.y = sigm(f0.y) * softp(s0.y);
            m.z = sigm(f1.x) * softp(s1.x);
            m.w = sigm(f1.y) * softp(s1.y);
            red4(hout + (size_t)dsts[t] * 128 + lane * 4, m);
        }
        __syncwarp();
    }
}

// ---------------- small utility kernels ----------------
__global__ void copy_kernel(const float* __restrict__ a, float* __restrict__ b, int n4) {
    int i = blockIdx.x * blockDim.x + threadIdx.x;
    if (i < n4) ((float4*)b)[i] = ((const float4*)a)[i];
}
__global__ void zero_kernel(float* __restrict__ p, int n) {
    int i = blockIdx.x * blockDim.x + threadIdx.x;
    if (i < n) p[i] = 0.f;
}
__global__ void pool_kernel(const float* __restrict__ h, const int* __restrict__ batch,
                            float* __restrict__ g) {
    int idx = blockIdx.x * blockDim.x + threadIdx.x;
    if (idx >= NN * 32) return;
    int node = idx >> 5, q = idx & 31;
    float4 v = ((const float4*)h)[idx];
    red4(g + (size_t)batch[node] * 128 + q * 4, v);
}
__global__ void out_kernel(const float* __restrict__ gf, const float* __restrict__ oW,
                           const float* __restrict__ ob, float* __restrict__ out) {
    int gidx = blockIdx.x * 8 + (threadIdx.x >> 5);
    int lane = threadIdx.x & 31;
    if (gidx >= NG) return;
    float s = 0.f;
#pragma unroll
    for (int k = lane; k < 128; k += 32) s += gf[gidx * 128 + k] * oW[k];
#pragma unroll
    for (int o = 16; o; o >>= 1) s += __shfl_down_sync(0xffffffffu, s, o);
    if (lane == 0) out[gidx] = s + ob[0];
}

// ---------------- launch ----------------
extern "C" void kernel_launch(void* const* d_in, const int* in_sizes, int n_in,
                              void* d_out, int out_size) {
    (void)in_sizes; (void)n_in; (void)out_size;
    const float* x   = (const float*)d_in[0];
    const int*   ei  = (const int*)d_in[1];
    const float* ea  = (const float*)d_in[2];
    const int*   bat = (const int*)d_in[3];
    const float* Wf  = (const float*)d_in[4];
    const float* bf  = (const float*)d_in[5];
    const float* Ws  = (const float*)d_in[6];
    const float* bs  = (const float*)d_in[7];
    const float* m1W0 = (const float*)d_in[8],  *m1b0 = (const float*)d_in[9];
    const float* m1W1 = (const float*)d_in[10], *m1b1 = (const float*)d_in[11];
    const float* m1Wp = (const float*)d_in[12], *m1bp = (const float*)d_in[13];
    const float* m2W0 = (const float*)d_in[14], *m2b0 = (const float*)d_in[15];
    const float* m2W1 = (const float*)d_in[16], *m2b1 = (const float*)d_in[17];
    const float* m2Wp = (const float*)d_in[18], *m2bp = (const float*)d_in[19];
    const float* oW   = (const float*)d_in[20], *ob   = (const float*)d_in[21];
    float* out = (float*)d_out;

    float *pH0, *pH1, *pP, *pW, *pB, *pPool, *pT0g, *pT1g, *pGf;
    cudaGetSymbolAddress((void**)&pH0,  g_h0);
    cudaGetSymbolAddress((void**)&pH1,  g_h1);
    cudaGetSymbolAddress((void**)&pP,   g_P);
    cudaGetSymbolAddress((void**)&pW,   g_Wcat);
    cudaGetSymbolAddress((void**)&pB,   g_bcat);
    cudaGetSymbolAddress((void**)&pPool, g_pool);
    cudaGetSymbolAddress((void**)&pT0g, g_t0g);
    cudaGetSymbolAddress((void**)&pT1g, g_t1g);
    cudaGetSymbolAddress((void**)&pGf,  g_gfin);

    cudaFuncSetAttribute(edge_kernel, cudaFuncAttributeMaxDynamicSharedMemorySize, 81920);

    const int MB = (NN + 127) / 128;   // 391

    // --- CGConv layer 0 ---
    pack_wcat<<<(512 * 128 + 255) / 256, 256>>>(Wf, Ws, bf, bs, pW, pB, 0);
    sgemm_bt<<<dim3(4, MB), 256>>>(x, pW, pB, nullptr, pP, NN, 512, 128, 0);
    copy_kernel<<<(NN * 32 + 255) / 256, 256>>>(x, pH0, NN * 32);
    edge_kernel<<<296, 256, 81920>>>(pP, ei, ea, Wf, Ws, 0, pH0);

    // --- CGConv layer 1 ---
    pack_wcat<<<(512 * 128 + 255) / 256, 256>>>(Wf, Ws, bf, bs, pW, pB, 1);
    sgemm_bt<<<dim3(4, MB), 256>>>(pH0, pW, pB, nullptr, pP, NN, 512, 128, 0);
    copy_kernel<<<(NN * 32 + 255) / 256, 256>>>(pH0, pH1, NN * 32);
    edge_kernel<<<296, 256, 81920>>>(pP, ei, ea, Wf, Ws, 1, pH1);

    // --- node MLP (residual) ---
    float* t0 = pP;
    float* t1 = pP + (size_t)NN * 256;
    sgemm_bt<<<dim3(2, MB), 256>>>(pH1, m1W0, m1b0, nullptr, t0, NN, 256, 128, 1);
    sgemm_bt<<<dim3(2, MB), 256>>>(t0, m1W1, m1b1, nullptr, t1, NN, 256, 256, 1);
    sgemm_bt<<<dim3(1, MB), 256>>>(t1, m1Wp, m1bp, pH1, pH0, NN, 128, 256, 0);

    // --- global add pool ---
    zero_kernel<<<(NG * 128 + 255) / 256, 256>>>(pPool, NG * 128);
    pool_kernel<<<(NN * 32 + 255) / 256, 256>>>(pH0, bat, pPool);

    // --- graph MLP (residual) + head ---
    sgemm_bt<<<dim3(2, 4), 256>>>(pPool, m2W0, m2b0, nullptr, pT0g, NG, 256, 128, 1);
    sgemm_bt<<<dim3(2, 4), 256>>>(pT0g, m2W1, m2b1, nullptr, pT1g, NG, 256, 256, 1);
    sgemm_bt<<<dim3(1, 4), 256>>>(pT1g, m2Wp, m2bp, pPool, pGf, NG, 128, 256, 0);
    out_kernel<<<64, 256>>>(pGf, oW, ob, out);
}